// round 3
// baseline (speedup 1.0000x reference)
#include <cuda_runtime.h>
#include <math_constants.h>

// Problem constants
#define BB 2
#define SQ 2048
#define EE 1024
#define HH 16
#define DD 64
#define MM (BB*SQ)   // 4096 rows

// Scratch (device globals: allocation-free rule)
__device__ float g_qh[BB*HH*SQ*DD];   // [B,H,S,D]
__device__ float g_kh[BB*HH*SQ*DD];
__device__ float g_vh[BB*HH*SQ*DD];
__device__ float g_att[BB*SQ*EE];     // attention context in [B,S,E]

// ---------------------------------------------------------------------------
// GEMM: C = A(MxK) @ W(NxK)^T (+bias). headmode=1 scatters to [B,H,S,D].
// 128x128 tile, BK=8, 256 threads, 8x8 register tile.
// ---------------------------------------------------------------------------
__global__ __launch_bounds__(256) void gemm_nt(
    const float* __restrict__ A, const float* __restrict__ W,
    const float* __restrict__ bias, float* __restrict__ C,
    int M, int N, int K, int headmode)
{
    __shared__ float As[8][128];
    __shared__ float Bs[8][128];
    const int m0 = blockIdx.y * 128;
    const int n0 = blockIdx.x * 128;
    const int tid = threadIdx.x;
    const int tr = tid >> 4;         // 0..15
    const int tc = tid & 15;         // 0..15
    const int lrow = tid >> 1;       // 0..127
    const int lseg = tid & 1;        // 0..1

    const float* Aptr = A + (size_t)(m0 + lrow) * K + lseg * 4;
    const float* Wptr = W + (size_t)(n0 + lrow) * K + lseg * 4;

    float acc[8][8];
    #pragma unroll
    for (int i = 0; i < 8; i++)
        #pragma unroll
        for (int j = 0; j < 8; j++) acc[i][j] = 0.f;

    for (int k0 = 0; k0 < K; k0 += 8) {
        float4 av = *(const float4*)(Aptr + k0);
        float4 wv = *(const float4*)(Wptr + k0);
        As[lseg*4+0][lrow] = av.x; As[lseg*4+1][lrow] = av.y;
        As[lseg*4+2][lrow] = av.z; As[lseg*4+3][lrow] = av.w;
        Bs[lseg*4+0][lrow] = wv.x; Bs[lseg*4+1][lrow] = wv.y;
        Bs[lseg*4+2][lrow] = wv.z; Bs[lseg*4+3][lrow] = wv.w;
        __syncthreads();
        #pragma unroll
        for (int kk = 0; kk < 8; kk++) {
            float a[8], b[8];
            *(float4*)(a)   = *(float4*)&As[kk][tr*8];
            *(float4*)(a+4) = *(float4*)&As[kk][tr*8+4];
            *(float4*)(b)   = *(float4*)&Bs[kk][tc*8];
            *(float4*)(b+4) = *(float4*)&Bs[kk][tc*8+4];
            #pragma unroll
            for (int i = 0; i < 8; i++)
                #pragma unroll
                for (int j = 0; j < 8; j++)
                    acc[i][j] += a[i]*b[j];
        }
        __syncthreads();
    }

    #pragma unroll
    for (int i = 0; i < 8; i++) {
        const int m = m0 + tr*8 + i;
        #pragma unroll
        for (int j = 0; j < 8; j++) {
            const int n = n0 + tc*8 + j;
            float v = acc[i][j];
            if (bias) v += bias[n];
            if (headmode) {
                const int b = m >> 11, s = m & 2047;
                const int h = n >> 6,  d = n & 63;
                C[((size_t)(b*HH + h)*SQ + s)*DD + d] = v;
            } else {
                C[(size_t)m*N + n] = v;
            }
        }
    }
}

// ---------------------------------------------------------------------------
// Flash attention (causal + ALiBi), fp32. One CTA = (64 q-rows, one b,h).
// 256 threads as 16x16 grid, 4x4 micro-tiles. Static smem: 48KB
// (K-transposed and P-transposed tiles alias the same buffer).
// ---------------------------------------------------------------------------
__global__ __launch_bounds__(256) void flash_kernel(
    const float* __restrict__ qh, const float* __restrict__ kh,
    const float* __restrict__ vh, float* __restrict__ att)
{
    __shared__ float Qt[64*64];    // [d][q]
    __shared__ float KPt[64*64];   // [d][c] for K, then [j][r] for P
    __shared__ float Vs[64*64];    // [j][c]

    const int qt = blockIdx.x;               // q tile, 0..31
    const int h  = blockIdx.y;
    const int b  = blockIdx.z;
    const int bh = b*HH + h;
    const float* Q = qh + (size_t)bh*SQ*DD + (size_t)qt*64*DD;
    const float* K = kh + (size_t)bh*SQ*DD;
    const float* V = vh + (size_t)bh*SQ*DD;

    const int tid = threadIdx.x;
    const int tr = tid >> 4, tc = tid & 15;
    const int r0 = tr*4, c0 = tc*4;

    // Load Q tile transposed
    #pragma unroll
    for (int i = 0; i < 4; i++) {
        const int g = tid + 256*i;
        const int row = g >> 4, c4 = (g & 15)*4;
        float4 v4 = *(const float4*)(Q + row*DD + c4);
        Qt[(c4+0)*64+row] = v4.x; Qt[(c4+1)*64+row] = v4.y;
        Qt[(c4+2)*64+row] = v4.z; Qt[(c4+3)*64+row] = v4.w;
    }

    float o[4][4];
    float m[4], l[4];
    #pragma unroll
    for (int i = 0; i < 4; i++) {
        m[i] = -CUDART_INF_F; l[i] = 0.f;
        #pragma unroll
        for (int j = 0; j < 4; j++) o[i][j] = 0.f;
    }
    const float slope = exp2f(-0.5f*(float)(h+1));

    for (int kt = 0; kt <= qt; kt++) {
        const float* Kp = K + (size_t)kt*64*DD;
        const float* Vp = V + (size_t)kt*64*DD;
        __syncthreads();   // previous PV reads done before overwrite
        #pragma unroll
        for (int i = 0; i < 4; i++) {
            const int g = tid + 256*i;
            const int row = g >> 4, c4 = (g & 15)*4;
            float4 kv = *(const float4*)(Kp + row*DD + c4);
            KPt[(c4+0)*64+row] = kv.x; KPt[(c4+1)*64+row] = kv.y;
            KPt[(c4+2)*64+row] = kv.z; KPt[(c4+3)*64+row] = kv.w;
            *(float4*)&Vs[row*64 + c4] = *(const float4*)(Vp + row*DD + c4);
        }
        __syncthreads();

        float s[4][4];
        #pragma unroll
        for (int i = 0; i < 4; i++)
            #pragma unroll
            for (int j = 0; j < 4; j++) s[i][j] = 0.f;

        #pragma unroll 8
        for (int d = 0; d < 64; d++) {
            float a[4], bb[4];
            *(float4*)a  = *(float4*)&Qt[d*64 + r0];
            *(float4*)bb = *(float4*)&KPt[d*64 + c0];
            #pragma unroll
            for (int i = 0; i < 4; i++)
                #pragma unroll
                for (int j = 0; j < 4; j++)
                    s[i][j] += a[i]*bb[j];
        }

        const int qbase = qt*64 + r0, kbase = kt*64 + c0;
        #pragma unroll
        for (int i = 0; i < 4; i++) {
            #pragma unroll
            for (int j = 0; j < 4; j++) {
                const int qi = qbase + i, kj = kbase + j;
                if (kj > qi) s[i][j] = -CUDART_INF_F;
                else s[i][j] = s[i][j]*0.125f - slope*(float)(qi - kj);
            }
        }

        // online softmax per row (16 lanes share a row group)
        #pragma unroll
        for (int i = 0; i < 4; i++) {
            float mx = fmaxf(fmaxf(s[i][0], s[i][1]), fmaxf(s[i][2], s[i][3]));
            #pragma unroll
            for (int off = 8; off; off >>= 1)
                mx = fmaxf(mx, __shfl_xor_sync(0xffffffffu, mx, off));
            const float mnew = fmaxf(m[i], mx);
            const float alpha = __expf(m[i] - mnew);
            float rs = 0.f;
            #pragma unroll
            for (int j = 0; j < 4; j++) {
                const float p = __expf(s[i][j] - mnew);
                s[i][j] = p; rs += p;
            }
            #pragma unroll
            for (int off = 8; off; off >>= 1)
                rs += __shfl_xor_sync(0xffffffffu, rs, off);
            l[i] = l[i]*alpha + rs;
            m[i] = mnew;
            #pragma unroll
            for (int j = 0; j < 4; j++) o[i][j] *= alpha;
        }

        // All threads done reading KPt as K (S-compute finished) before
        // overwriting it with P-transposed.
        __syncthreads();
        #pragma unroll
        for (int i = 0; i < 4; i++)
            #pragma unroll
            for (int j = 0; j < 4; j++)
                KPt[(c0+j)*64 + (r0+i)] = s[i][j];
        __syncthreads();

        // O += P @ V
        #pragma unroll 8
        for (int jj = 0; jj < 64; jj++) {
            float p4[4], v4[4];
            *(float4*)p4 = *(float4*)&KPt[jj*64 + r0];
            *(float4*)v4 = *(float4*)&Vs[jj*64 + c0];
            #pragma unroll
            for (int i = 0; i < 4; i++)
                #pragma unroll
                for (int j = 0; j < 4; j++)
                    o[i][j] += p4[i]*v4[j];
        }
    }

    // normalize + store to [B,S,E] context buffer
    #pragma unroll
    for (int i = 0; i < 4; i++) {
        const float inv = 1.f / l[i];
        const int qi = qt*64 + r0 + i;
        float* outp = att + ((size_t)(b*SQ + qi))*EE + h*DD + c0;
        float4 w;
        w.x = o[i][0]*inv; w.y = o[i][1]*inv;
        w.z = o[i][2]*inv; w.w = o[i][3]*inv;
        *(float4*)outp = w;
    }
}

// ---------------------------------------------------------------------------
// Head-0 attention probabilities (second output). One CTA per (query row, b).
// ---------------------------------------------------------------------------
__global__ __launch_bounds__(256) void attn0_kernel(
    const float* __restrict__ qh, const float* __restrict__ kh,
    float* __restrict__ attn_out)
{
    __shared__ float qrow[64];
    __shared__ float lg[SQ];
    __shared__ float redmax[8];
    __shared__ float redsum[8];

    const int i = blockIdx.x;
    const int b = blockIdx.y;
    const float* Q = qh + ((size_t)(b*HH)*SQ + i)*DD;
    const float* K = kh + (size_t)(b*HH)*SQ*DD;
    const int tid = threadIdx.x;

    if (tid < 64) qrow[tid] = Q[tid];
    __syncthreads();

    const float slope = 0.70710678118654752f;  // 2^-0.5 (head 1 of 16)
    float lmax = -CUDART_INF_F;
    for (int j = tid; j <= i; j += 256) {
        const float4* kp = (const float4*)(K + (size_t)j*DD);
        float dot = 0.f;
        #pragma unroll
        for (int d4 = 0; d4 < 16; d4++) {
            float4 kv = kp[d4];
            float4 qv = *(const float4*)&qrow[d4*4];
            dot += kv.x*qv.x + kv.y*qv.y + kv.z*qv.z + kv.w*qv.w;
        }
        const float v = dot*0.125f - slope*(float)(i - j);
        lg[j] = v;
        lmax = fmaxf(lmax, v);
    }
    // block max
    #pragma unroll
    for (int off = 16; off; off >>= 1)
        lmax = fmaxf(lmax, __shfl_xor_sync(0xffffffffu, lmax, off));
    if ((tid & 31) == 0) redmax[tid >> 5] = lmax;
    __syncthreads();
    float gmax = redmax[0];
    #pragma unroll
    for (int w = 1; w < 8; w++) gmax = fmaxf(gmax, redmax[w]);

    float psum = 0.f;
    for (int j = tid; j <= i; j += 256) {
        const float p = __expf(lg[j] - gmax);
        lg[j] = p;
        psum += p;
    }
    #pragma unroll
    for (int off = 16; off; off >>= 1)
        psum += __shfl_xor_sync(0xffffffffu, psum, off);
    if ((tid & 31) == 0) redsum[tid >> 5] = psum;
    __syncthreads();
    float gsum = 0.f;
    #pragma unroll
    for (int w = 0; w < 8; w++) gsum += redsum[w];
    const float inv = 1.f / gsum;

    float* outp = attn_out + ((size_t)(b*SQ + i))*SQ;
    for (int j = tid; j < SQ; j += 256)
        outp[j] = (j <= i) ? lg[j]*inv : 0.f;
}

// ---------------------------------------------------------------------------
extern "C" void kernel_launch(void* const* d_in, const int* in_sizes, int n_in,
                              void* d_out, int out_size)
{
    const float* q  = (const float*)d_in[0];
    const float* k  = (const float*)d_in[1];
    const float* v  = (const float*)d_in[2];
    // d_in[3] = alibi, d_in[4] = mask  (computed analytically in-kernel)
    const float* wq = (const float*)d_in[5];
    const float* wk = (const float*)d_in[6];
    const float* wv = (const float*)d_in[7];
    const float* wd = (const float*)d_in[8];
    const float* bd = (const float*)d_in[9];

    float *qh, *kh, *vh, *att;
    cudaGetSymbolAddress((void**)&qh,  g_qh);
    cudaGetSymbolAddress((void**)&kh,  g_kh);
    cudaGetSymbolAddress((void**)&vh,  g_vh);
    cudaGetSymbolAddress((void**)&att, g_att);

    float* out_main = (float*)d_out;                       // [B,S,E]
    float* out_attn = (float*)d_out + (size_t)MM*EE;       // [B,S,S]

    const dim3 gemm_grid(EE/128, MM/128);   // 8 x 32

    gemm_nt<<<gemm_grid, 256>>>(q, wq, nullptr, qh, MM, EE, EE, 1);
    gemm_nt<<<gemm_grid, 256>>>(k, wk, nullptr, kh, MM, EE, EE, 1);
    gemm_nt<<<gemm_grid, 256>>>(v, wv, nullptr, vh, MM, EE, EE, 1);

    flash_kernel<<<dim3(SQ/64, HH, BB), 256>>>(qh, kh, vh, att);

    attn0_kernel<<<dim3(SQ, BB), 256>>>(qh, kh, out_attn);

    gemm_nt<<<gemm_grid, 256>>>(att, wd, bd, out_main, MM, EE, EE, 0);
}